// round 8
// baseline (speedup 1.0000x reference)
#include <cuda_runtime.h>

// Problem constants
#define HID     50
#define NG      200
#define IN0     17
#define SDIM    16
#define TSTEPS  128
#define FC1N    25

// Tiling: two independent 32-row halves, 7 warps each, RPT=16
#define ROWS      64
#define HROWS     32
#define NTHREADS  448
#define HTHREADS  224
#define NPAIR     8       // 8 float2 pairs = 16 rows per slot

// Strides
#define FC1_S     51
#define TSTRIDE   68      // 272B rows, 16B-aligned
#define WI2_S     9       // wih0 row stride in float2 (17 -> 9 with zero pad)
#define WH2_S     27      // hh row stride in float2  (50 -> 25 + 2 pad); 27%16=11, gcd(11,16)=1
#define GB0F      450     // f2 block stride wih0 (50*9)
#define GBHF      1350    // f2 block stride hh   (50*27)

typedef unsigned long long ull;

__device__ __forceinline__ ull pack2(float a, float b) {
    ull r; asm("mov.b64 %0,{%1,%2};" : "=l"(r) : "f"(a), "f"(b)); return r;
}
__device__ __forceinline__ float2 unpk(ull v) {
    float2 f; asm("mov.b64 {%0,%1},%2;" : "=f"(f.x), "=f"(f.y) : "l"(v)); return f;
}
__device__ __forceinline__ void fma2(ull& d, ull a, ull b) {
    asm("fma.rn.f32x2 %0,%1,%2,%0;" : "+l"(d) : "l"(a), "l"(b));
}
__device__ __forceinline__ void add2(ull& d, ull a) {
    asm("add.rn.f32x2 %0,%0,%1;" : "+l"(d) : "l"(a));
}
__device__ __forceinline__ float tanh_a(float x) {
    float y; asm("tanh.approx.f32 %0,%1;" : "=f"(y) : "f"(x)); return y;
}
__device__ __forceinline__ float sig_a(float x) {
    return fmaf(tanh_a(0.5f * x), 0.5f, 0.5f);
}
__device__ __forceinline__ void half_bar(int half) {
    asm volatile("bar.sync %0, %1;" :: "r"(half + 1), "r"(HTHREADS) : "memory");
}

// Shared layout (float offsets; all float2 regions 8B aligned, x/h rows 16B aligned)
#define OFF_WIH0   0         // 3600 floats (1800 f2)
#define OFF_WHH0   3600      // 10800 floats
#define OFF_WIH1   14400     // 10800
#define OFF_WHH1   25200     // 10800
#define OFF_FC1    36000     // 1275
#define OFF_FC2    37276     // 25
#define OFF_B0     37302     // 200
#define OFF_B1     37502     // 200
#define OFF_BFC1   37702     // 25
#define OFF_BFC2   37728     // 2
#define OFF_X      37732     // 18*68 = 1224 (row 17 = zero pad for k-pairing)
#define OFF_H0     38956     // 2*50*68 = 6800
#define OFF_H1     45756     // 6800
#define SMEM_FLOATS 52556    // 210224 bytes

// One k-pair of gate MACs: weights (float2: k, k+1), state rows k and k+1
#define GATE2(PA, PB, SBASE) do { \
    float2 wa_ = (PA)[kk], wb_ = (PB)[kk]; \
    ull wax_ = pack2(wa_.x, wa_.x), wbx_ = pack2(wb_.x, wb_.x); \
    ull way_ = pack2(wa_.y, wa_.y), wby_ = pack2(wb_.y, wb_.y); \
    const float* s0_ = (SBASE); \
    ulonglong2 u0_ = *(const ulonglong2*)(s0_); \
    ulonglong2 u1_ = *(const ulonglong2*)(s0_ + 4); \
    ulonglong2 u2_ = *(const ulonglong2*)(s0_ + 8); \
    ulonglong2 u3_ = *(const ulonglong2*)(s0_ + 12); \
    fma2(a0[0], wax_, u0_.x); fma2(a0[1], wax_, u0_.y); \
    fma2(a0[2], wax_, u1_.x); fma2(a0[3], wax_, u1_.y); \
    fma2(a0[4], wax_, u2_.x); fma2(a0[5], wax_, u2_.y); \
    fma2(a0[6], wax_, u3_.x); fma2(a0[7], wax_, u3_.y); \
    fma2(a1[0], wbx_, u0_.x); fma2(a1[1], wbx_, u0_.y); \
    fma2(a1[2], wbx_, u1_.x); fma2(a1[3], wbx_, u1_.y); \
    fma2(a1[4], wbx_, u2_.x); fma2(a1[5], wbx_, u2_.y); \
    fma2(a1[6], wbx_, u3_.x); fma2(a1[7], wbx_, u3_.y); \
    const float* s1_ = s0_ + TSTRIDE; \
    ulonglong2 v0_ = *(const ulonglong2*)(s1_); \
    ulonglong2 v1_ = *(const ulonglong2*)(s1_ + 4); \
    ulonglong2 v2_ = *(const ulonglong2*)(s1_ + 8); \
    ulonglong2 v3_ = *(const ulonglong2*)(s1_ + 12); \
    fma2(a0[0], way_, v0_.x); fma2(a0[1], way_, v0_.y); \
    fma2(a0[2], way_, v1_.x); fma2(a0[3], way_, v1_.y); \
    fma2(a0[4], way_, v2_.x); fma2(a0[5], way_, v2_.y); \
    fma2(a0[6], way_, v3_.x); fma2(a0[7], way_, v3_.y); \
    fma2(a1[0], wby_, v0_.x); fma2(a1[1], wby_, v0_.y); \
    fma2(a1[2], wby_, v1_.x); fma2(a1[3], wby_, v1_.y); \
    fma2(a1[4], wby_, v2_.x); fma2(a1[5], wby_, v2_.y); \
    fma2(a1[6], wby_, v3_.x); fma2(a1[7], wby_, v3_.y); \
} while (0)

// Gate exchange + LSTM nonlinearity for 8 pairs (thread keeps pairs 4*gs..4*gs+3)
#define EPILOGUE(LYR, HDST) do { \
    ull sx_[8], rx_[8]; \
    _Pragma("unroll") \
    for (int q = 0; q < 4; q++) { \
        sx_[q]     = gs ? a0[q] : a0[4 + q]; \
        sx_[4 + q] = gs ? a1[q] : a1[4 + q]; \
    } \
    _Pragma("unroll") \
    for (int q = 0; q < 8; q++) rx_[q] = __shfl_xor_sync(0xffffffffu, sx_[q], 16); \
    float hv_[8]; \
    _Pragma("unroll") \
    for (int lp = 0; lp < 4; lp++) { \
        ull gi_ = gs ? rx_[lp]     : a0[lp]; \
        ull gf_ = gs ? rx_[4 + lp] : a1[lp]; \
        ull gg_ = gs ? a0[4 + lp]  : rx_[lp]; \
        ull go_ = gs ? a1[4 + lp]  : rx_[4 + lp]; \
        float2 vi_ = unpk(gi_), vf_ = unpk(gf_), vg_ = unpk(gg_), vo_ = unpk(go_); \
        float ncx_ = sig_a(vf_.x) * cx[LYR][lp] + sig_a(vi_.x) * tanh_a(vg_.x); \
        float ncy_ = sig_a(vf_.y) * cy[LYR][lp] + sig_a(vi_.y) * tanh_a(vg_.y); \
        cx[LYR][lp] = ncx_; cy[LYR][lp] = ncy_; \
        hv_[2*lp]     = sig_a(vo_.x) * tanh_a(ncx_); \
        hv_[2*lp + 1] = sig_a(vo_.y) * tanh_a(ncy_); \
    } \
    if (!dup) { \
        float* dst_ = &(HDST)[j * TSTRIDE + r0 + 8 * gs]; \
        float4 q0_; q0_.x = hv_[0]; q0_.y = hv_[1]; q0_.z = hv_[2]; q0_.w = hv_[3]; \
        float4 q1_; q1_.x = hv_[4]; q1_.y = hv_[5]; q1_.z = hv_[6]; q1_.w = hv_[7]; \
        *(float4*)dst_ = q0_; *(float4*)(dst_ + 4) = q1_; \
    } \
} while (0)

__global__ __launch_bounds__(NTHREADS, 1)
void kozyra_lstm_kernel(const float* __restrict__ features,
                        const float* __restrict__ w_ih0, const float* __restrict__ w_hh0,
                        const float* __restrict__ b0,
                        const float* __restrict__ w_ih1, const float* __restrict__ w_hh1,
                        const float* __restrict__ b1,
                        const float* __restrict__ w_fc1, const float* __restrict__ b_fc1,
                        const float* __restrict__ w_fc2, const float* __restrict__ b_fc2,
                        float* __restrict__ out)
{
    extern __shared__ float sm[];
    float* s_fc1  = sm + OFF_FC1;
    float* s_fc2  = sm + OFF_FC2;
    float* s_b0   = sm + OFF_B0;
    float* s_b1   = sm + OFF_B1;
    float* s_bfc1 = sm + OFF_BFC1;
    float* s_bfc2 = sm + OFF_BFC2;
    float* s_x    = sm + OFF_X;      // [18][TSTRIDE], row 16 = delta, row 17 = zeros
    float* s_h0b  = sm + OFF_H0;     // 2 x [HID][TSTRIDE]
    float* s_h1b  = sm + OFF_H1;

    const int tid  = threadIdx.x;
    const int brow = blockIdx.x * ROWS;

    // ---- Stage weights as float2-paired, per-gate blocks (order I G F O) ----
    // gate->block map {0:0, 1:2, 2:1, 3:3} (involution)
    for (int i = tid; i < 4 * HID * WI2_S * 2; i += NTHREADS) {
        int f2i = i >> 1, lo = i & 1;
        int blk = f2i / GB0F, rem = f2i % GB0F;
        int jj = rem / WI2_S, kk = rem % WI2_S;
        int k = 2 * kk + lo;
        int gate = (blk == 1) ? 2 : (blk == 2) ? 1 : blk;
        sm[OFF_WIH0 + f2i * 2 + lo] = (k < IN0) ? w_ih0[(gate * HID + jj) * IN0 + k] : 0.0f;
    }
    for (int i = tid; i < 4 * HID * WH2_S * 2; i += NTHREADS) {
        int f2i = i >> 1, lo = i & 1;
        int blk = f2i / GBHF, rem = f2i % GBHF;
        int jj = rem / WH2_S, kk = rem % WH2_S;
        int k = 2 * kk + lo;
        int gate = (blk == 1) ? 2 : (blk == 2) ? 1 : blk;
        bool ok = (k < HID);
        int src = (gate * HID + jj) * HID + (ok ? k : 0);
        sm[OFF_WHH0 + f2i * 2 + lo] = ok ? w_hh0[src] : 0.0f;
        sm[OFF_WIH1 + f2i * 2 + lo] = ok ? w_ih1[src] : 0.0f;
        sm[OFF_WHH1 + f2i * 2 + lo] = ok ? w_hh1[src] : 0.0f;
    }
    for (int i = tid; i < FC1N * HID; i += NTHREADS) {
        int n = i / HID, k = i % HID;
        s_fc1[n * FC1_S + k] = w_fc1[i];
    }
    for (int i = tid; i < FC1N; i += NTHREADS) { s_fc2[i] = w_fc2[i]; s_bfc1[i] = b_fc1[i]; }
    for (int i = tid; i < NG;   i += NTHREADS) { s_b0[i] = b0[i]; s_b1[i] = b1[i]; }
    if (tid == 0) s_bfc2[0] = b_fc2[0];

    // ---- Init state + x (incl. zero pad rows) ----
    for (int i = tid; i < 2 * HID * TSTRIDE; i += NTHREADS) { s_h0b[i] = 0.0f; s_h1b[i] = 0.0f; }
    for (int i = tid; i < 18 * TSTRIDE; i += NTHREADS) s_x[i] = 0.0f;
    __syncthreads();
    const float* fbase = features + (size_t)brow * (TSTEPS * SDIM);
    for (int i = tid; i < ROWS * SDIM; i += NTHREADS) {
        int r = i >> 4, s = i & 15;
        s_x[s * TSTRIDE + r] = fbase[(size_t)r * (TSTEPS * SDIM) + s];
    }
    __syncthreads();   // last full-block barrier

    // ---- Thread mapping: half (7 warps, 32 rows), RPT=16 ----
    const int w    = tid >> 5;
    const int lane = tid & 31;
    const int half = (w >= 7) ? 1 : 0;
    const int hw   = w - half * 7;
    const int gs   = lane >> 4;
    const int sub  = lane & 15;
    int rg, j; bool dup = false;
    if (hw < 6) { rg = hw / 3; j = (hw % 3) * 16 + sub; }
    else { int s4 = sub & 3; dup = (sub >= 4); rg = s4 >> 1; j = 48 + (s4 & 1); }
    const int r0 = half * HROWS + rg * 16;
    const int hbase = half * HROWS;

    const float2* w2 = (const float2*)sm;
    const float2* pAx  = w2 + gs * GB0F + j * WI2_S;                 // wih0
    const float2* pBx  = pAx + 2 * GB0F;
    const float2* pAh0 = w2 + (OFF_WHH0 / 2) + gs * GBHF + j * WH2_S;
    const float2* pBh0 = pAh0 + 2 * GBHF;
    const float2* pAi1 = w2 + (OFF_WIH1 / 2) + gs * GBHF + j * WH2_S;
    const float2* pBi1 = pAi1 + 2 * GBHF;
    const float2* pAh1 = w2 + (OFF_WHH1 / 2) + gs * GBHF + j * WH2_S;
    const float2* pBh1 = pAh1 + 2 * GBHF;

    const float bA0 = s_b0[(gs ? 2 : 0) * HID + j];
    const float bB0 = s_b0[(gs ? 3 : 1) * HID + j];
    const float bA1 = s_b1[(gs ? 2 : 0) * HID + j];
    const float bB1 = s_b1[(gs ? 3 : 1) * HID + j];
    const ull bpA0 = pack2(bA0, bA0), bpB0 = pack2(bB0, bB0);
    const ull bpA1 = pack2(bA1, bA1), bpB1 = pack2(bB1, bB1);

    float cx[2][4], cy[2][4];
    #pragma unroll
    for (int L = 0; L < 2; L++)
        #pragma unroll
        for (int p = 0; p < 4; p++) { cx[L][p] = 0.0f; cy[L][p] = 0.0f; }

    for (int t = 0; t < TSTEPS; t++) {
        const int pb = t & 1;
        float* h0r = s_h0b + pb * (HID * TSTRIDE);
        float* h0w = s_h0b + (pb ^ 1) * (HID * TSTRIDE);
        float* h1r = s_h1b + pb * (HID * TSTRIDE);
        float* h1w = s_h1b + (pb ^ 1) * (HID * TSTRIDE);

        ull a0[NPAIR], a1[NPAIR];

        // ================= Layer 0 =================
        #pragma unroll
        for (int p = 0; p < NPAIR; p++) { a0[p] = bpA0; a1[p] = bpB0; }
        #pragma unroll
        for (int kk = 0; kk < 9; kk++)          // k = 0..17 (17 = zero pad)
            GATE2(pAx, pBx, &s_x[(2 * kk) * TSTRIDE + r0]);
        #pragma unroll 5
        for (int kk = 0; kk < 25; kk++)
            GATE2(pAh0, pBh0, &h0r[(2 * kk) * TSTRIDE + r0]);
        EPILOGUE(0, h0w);
        half_bar(half);   // h0 rows of this half visible

        // ================= Layer 1 =================
        #pragma unroll
        for (int p = 0; p < NPAIR; p++) { a0[p] = bpA1; a1[p] = bpB1; }
        #pragma unroll 5
        for (int kk = 0; kk < 25; kk++)
            GATE2(pAi1, pBi1, &h0w[(2 * kk) * TSTRIDE + r0]);
        #pragma unroll 5
        for (int kk = 0; kk < 25; kk++)
            GATE2(pAh1, pBh1, &h1r[(2 * kk) * TSTRIDE + r0]);
        EPILOGUE(1, h1w);
        half_bar(half);   // h1 rows of this half visible

        // ========= fc (warps 0-3, oct-row tasks) + feature prefetch (warps 4-6) =========
        const bool has_next = (t + 1 < TSTEPS);
        if (hw < 4) {
            const int rb = hbase + hw * 8;     // 8 rows
            ull ac0 = 0ULL, ac1 = 0ULL, ac2 = 0ULL, ac3 = 0ULL;
            if (lane < FC1N) {
                float bb1 = s_bfc1[lane];
                ac0 = pack2(bb1, bb1); ac1 = ac0; ac2 = ac0; ac3 = ac0;
                const float* wr = &s_fc1[lane * FC1_S];
                #pragma unroll 10
                for (int k = 0; k < HID; k++) {
                    float wv = wr[k];
                    ull wp = pack2(wv, wv);
                    const float* hb = &h1w[k * TSTRIDE + rb];
                    ulonglong2 hA = *(const ulonglong2*)(hb);
                    ulonglong2 hB = *(const ulonglong2*)(hb + 4);
                    fma2(ac0, wp, hA.x); fma2(ac1, wp, hA.y);
                    fma2(ac2, wp, hB.x); fma2(ac3, wp, hB.y);
                }
                float sc = s_fc2[lane];
                float2 u0 = unpk(ac0), u1 = unpk(ac1), u2 = unpk(ac2), u3 = unpk(ac3);
                u0.x = fmaxf(u0.x, 0.0f) * sc;  u0.y = fmaxf(u0.y, 0.0f) * sc;
                u1.x = fmaxf(u1.x, 0.0f) * sc;  u1.y = fmaxf(u1.y, 0.0f) * sc;
                u2.x = fmaxf(u2.x, 0.0f) * sc;  u2.y = fmaxf(u2.y, 0.0f) * sc;
                u3.x = fmaxf(u3.x, 0.0f) * sc;  u3.y = fmaxf(u3.y, 0.0f) * sc;
                ac0 = pack2(u0.x, u0.y); ac1 = pack2(u1.x, u1.y);
                ac2 = pack2(u2.x, u2.y); ac3 = pack2(u3.x, u3.y);
            }
            #pragma unroll
            for (int off = 16; off > 0; off >>= 1) {
                add2(ac0, __shfl_down_sync(0xffffffffu, ac0, off));
                add2(ac1, __shfl_down_sync(0xffffffffu, ac1, off));
                add2(ac2, __shfl_down_sync(0xffffffffu, ac2, off));
                add2(ac3, __shfl_down_sync(0xffffffffu, ac3, off));
            }
            if (lane == 0) {
                float bb = s_bfc2[0];
                float2 d0 = unpk(ac0), d1 = unpk(ac1), d2 = unpk(ac2), d3 = unpk(ac3);
                float4 q0; q0.x = d0.x + bb; q0.y = d0.y + bb; q0.z = d1.x + bb; q0.w = d1.y + bb;
                float4 q1; q1.x = d2.x + bb; q1.y = d2.y + bb; q1.z = d3.x + bb; q1.w = d3.y + bb;
                *(float4*)&s_x[SDIM * TSTRIDE + rb]     = q0;   // delta -> next x
                *(float4*)&s_x[SDIM * TSTRIDE + rb + 4] = q1;
                out[(size_t)(brow + rb)     * TSTEPS + t] = q0.x;
                out[(size_t)(brow + rb + 1) * TSTEPS + t] = q0.y;
                out[(size_t)(brow + rb + 2) * TSTEPS + t] = q0.z;
                out[(size_t)(brow + rb + 3) * TSTEPS + t] = q0.w;
                out[(size_t)(brow + rb + 4) * TSTEPS + t] = q1.x;
                out[(size_t)(brow + rb + 5) * TSTEPS + t] = q1.y;
                out[(size_t)(brow + rb + 6) * TSTEPS + t] = q1.z;
                out[(size_t)(brow + rb + 7) * TSTEPS + t] = q1.w;
            }
        } else if (has_next) {
            // warps 4-6: prefetch next timestep's features for this half (512 elems, 96 thr)
            int idx = (hw - 4) * 32 + lane;    // 0..95
            #pragma unroll
            for (int ii = 0; ii < 6; ii++) {
                int e = idx + ii * 96;
                if (e < HROWS * SDIM) {
                    int r = e >> 4, s = e & 15;
                    s_x[s * TSTRIDE + hbase + r] =
                        fbase[(size_t)(hbase + r) * (TSTEPS * SDIM) + (size_t)(t + 1) * SDIM + s];
                }
            }
        }
        half_bar(half);   // delta + x(t+1) visible within half
    }
}

extern "C" void kernel_launch(void* const* d_in, const int* in_sizes, int n_in,
                              void* d_out, int out_size)
{
    const float* features = (const float*)d_in[0];
    const float* w_ih0    = (const float*)d_in[1];
    const float* w_hh0    = (const float*)d_in[2];
    const float* b0       = (const float*)d_in[3];
    const float* w_ih1    = (const float*)d_in[4];
    const float* w_hh1    = (const float*)d_in[5];
    const float* b1       = (const float*)d_in[6];
    const float* w_fc1    = (const float*)d_in[7];
    const float* b_fc1    = (const float*)d_in[8];
    const float* w_fc2    = (const float*)d_in[9];
    const float* b_fc2    = (const float*)d_in[10];
    float* out = (float*)d_out;

    const int batch = in_sizes[0] / (TSTEPS * SDIM);
    const int nblocks = batch / ROWS;

    const size_t smem_bytes = SMEM_FLOATS * sizeof(float);
    cudaFuncSetAttribute(kozyra_lstm_kernel,
                         cudaFuncAttributeMaxDynamicSharedMemorySize,
                         (int)smem_bytes);

    kozyra_lstm_kernel<<<nblocks, NTHREADS, smem_bytes>>>(
        features, w_ih0, w_hh0, b0, w_ih1, w_hh1, b1,
        w_fc1, b_fc1, w_fc2, b_fc2, out);
}

// round 10
// speedup vs baseline: 1.8142x; 1.8142x over previous
#include <cuda_runtime.h>

// Problem constants
#define HID     50
#define NG      200
#define IN0     17
#define SDIM    16
#define TSTEPS  128
#define FC1N    25

// Tiling: two independent 32-row halves, 13 warps each (R7 structure)
#define ROWS      64
#define HROWS     32
#define NTHREADS  832
#define HTHREADS  416

// Strides
#define FC1_S     51
#define TSTRIDE   68      // floats; 272B rows, 16B-aligned
#define W4I_S     17      // wih0 float4 stride per j (17 mod 8 = 1)
#define W4H_S     51      // hh float4 stride per j   (51 mod 8 = 3)

typedef unsigned long long ull;

__device__ __forceinline__ ull pack2(float a, float b) {
    ull r; asm("mov.b64 %0,{%1,%2};" : "=l"(r) : "f"(a), "f"(b)); return r;
}
__device__ __forceinline__ float2 unpk(ull v) {
    float2 f; asm("mov.b64 {%0,%1},%2;" : "=f"(f.x), "=f"(f.y) : "l"(v)); return f;
}
__device__ __forceinline__ void fma2(ull& d, ull a, ull b) {
    asm("fma.rn.f32x2 %0,%1,%2,%0;" : "+l"(d) : "l"(a), "l"(b));
}
__device__ __forceinline__ void add2(ull& d, ull a) {
    asm("add.rn.f32x2 %0,%0,%1;" : "+l"(d) : "l"(a));
}
__device__ __forceinline__ float tanh_a(float x) {
    float y; asm("tanh.approx.f32 %0,%1;" : "=f"(y) : "f"(x)); return y;
}
__device__ __forceinline__ float sig_a(float x) {
    return fmaf(tanh_a(0.5f * x), 0.5f, 0.5f);
}
__device__ __forceinline__ void half_bar(int half) {
    asm volatile("bar.sync %0, %1;" :: "r"(half + 1), "r"(HTHREADS) : "memory");
}

// Shared layout (float offsets; float4 regions 16B aligned)
#define OFF_W4_IH0 0         // 50*17 f4 = 3400 floats
#define OFF_W4_HH0 3400      // 50*51 f4 = 10200 floats
#define OFF_W4_IH1 13600     // 10200
#define OFF_W4_HH1 23800     // 10200
#define OFF_FC1    34000     // 1275
#define OFF_FC2    35276     // 25
#define OFF_B0     35302     // 200
#define OFF_B1     35502     // 200
#define OFF_BFC1   35702     // 25
#define OFF_BFC2   35728     // 2 (+2 pad)
#define OFF_X      35732     // 17*68 = 1156  (16B aligned)
#define OFF_H0     36888     // 2*50*68 = 6800
#define OFF_H1     43688     // 6800
#define SMEM_FLOATS 50488    // 201952 bytes

// One k of gate MACs: float4 weights (4 gates), one LDS.128 of state (4 rows)
#define GATEK(PW, SBASE, K) do { \
    float4 wv_ = (PW)[K]; \
    ull wi_ = pack2(wv_.x, wv_.x), wf_ = pack2(wv_.y, wv_.y); \
    ull wg_ = pack2(wv_.z, wv_.z), wo_ = pack2(wv_.w, wv_.w); \
    ulonglong2 sv_ = *(const ulonglong2*)((SBASE) + (K) * TSTRIDE); \
    fma2(ai[0], wi_, sv_.x); fma2(ai[1], wi_, sv_.y); \
    fma2(af[0], wf_, sv_.x); fma2(af[1], wf_, sv_.y); \
    fma2(ag[0], wg_, sv_.x); fma2(ag[1], wg_, sv_.y); \
    fma2(ao[0], wo_, sv_.x); fma2(ao[1], wo_, sv_.y); \
} while (0)

// LSTM nonlinearity for this thread's 4 rows (2 f32x2 pairs); no gate exchange needed
#define EPILOGUE(LYR, HDST) do { \
    float hv_[4]; \
    _Pragma("unroll") \
    for (int p = 0; p < 2; p++) { \
        float2 vi_ = unpk(ai[p]), vf_ = unpk(af[p]); \
        float2 vg_ = unpk(ag[p]), vo_ = unpk(ao[p]); \
        float ncx_ = sig_a(vf_.x) * cx[LYR][p] + sig_a(vi_.x) * tanh_a(vg_.x); \
        float ncy_ = sig_a(vf_.y) * cy[LYR][p] + sig_a(vi_.y) * tanh_a(vg_.y); \
        cx[LYR][p] = ncx_; cy[LYR][p] = ncy_; \
        hv_[2*p]     = sig_a(vo_.x) * tanh_a(ncx_); \
        hv_[2*p + 1] = sig_a(vo_.y) * tanh_a(ncy_); \
    } \
    if (!dup) { \
        float4 q_; q_.x = hv_[0]; q_.y = hv_[1]; q_.z = hv_[2]; q_.w = hv_[3]; \
        *(float4*)&(HDST)[j * TSTRIDE + r0] = q_; \
    } \
} while (0)

__global__ __launch_bounds__(NTHREADS, 1)
void kozyra_lstm_kernel(const float* __restrict__ features,
                        const float* __restrict__ w_ih0, const float* __restrict__ w_hh0,
                        const float* __restrict__ b0,
                        const float* __restrict__ w_ih1, const float* __restrict__ w_hh1,
                        const float* __restrict__ b1,
                        const float* __restrict__ w_fc1, const float* __restrict__ b_fc1,
                        const float* __restrict__ w_fc2, const float* __restrict__ b_fc2,
                        float* __restrict__ out)
{
    extern __shared__ float sm[];
    float* s_fc1  = sm + OFF_FC1;
    float* s_fc2  = sm + OFF_FC2;
    float* s_b0   = sm + OFF_B0;
    float* s_b1   = sm + OFF_B1;
    float* s_bfc1 = sm + OFF_BFC1;
    float* s_bfc2 = sm + OFF_BFC2;
    float* s_x    = sm + OFF_X;      // [IN0][TSTRIDE], row 16 = delta
    float* s_h0b  = sm + OFF_H0;     // 2 x [HID][TSTRIDE]
    float* s_h1b  = sm + OFF_H1;

    const int tid  = threadIdx.x;
    const int brow = blockIdx.x * ROWS;

    // ---- Stage weights interleaved as float4 (wi,wf,wg,wo) per (j,k) ----
    for (int i = tid; i < HID * IN0 * 4; i += NTHREADS) {
        int gate = i & 3, rest = i >> 2;
        int j = rest / IN0, k = rest % IN0;
        sm[OFF_W4_IH0 + (j * W4I_S + k) * 4 + gate] = w_ih0[(gate * HID + j) * IN0 + k];
    }
    for (int i = tid; i < HID * W4H_S * 4; i += NTHREADS) {
        int gate = i & 3, rest = i >> 2;
        int j = rest / W4H_S, k = rest % W4H_S;
        float v0 = 0.0f, v1 = 0.0f, v2 = 0.0f;
        if (k < HID) {
            int src = (gate * HID + j) * HID + k;
            v0 = w_hh0[src]; v1 = w_ih1[src]; v2 = w_hh1[src];
        }
        int o = (j * W4H_S + k) * 4 + gate;
        sm[OFF_W4_HH0 + o] = v0;
        sm[OFF_W4_IH1 + o] = v1;
        sm[OFF_W4_HH1 + o] = v2;
    }
    for (int i = tid; i < FC1N * HID; i += NTHREADS) {
        int n = i / HID, k = i % HID;
        s_fc1[n * FC1_S + k] = w_fc1[i];
    }
    for (int i = tid; i < FC1N; i += NTHREADS) { s_fc2[i] = w_fc2[i]; s_bfc1[i] = b_fc1[i]; }
    for (int i = tid; i < NG;   i += NTHREADS) { s_b0[i] = b0[i]; s_b1[i] = b1[i]; }
    if (tid == 0) s_bfc2[0] = b_fc2[0];

    // ---- Init state + x for t=0 ----
    for (int i = tid; i < 2 * HID * TSTRIDE; i += NTHREADS) { s_h0b[i] = 0.0f; s_h1b[i] = 0.0f; }
    const float* fbase = features + (size_t)brow * (TSTEPS * SDIM);
    for (int i = tid; i < ROWS * SDIM; i += NTHREADS) {
        int r = i >> 4, s = i & 15;
        s_x[s * TSTRIDE + r] = fbase[(size_t)r * (TSTEPS * SDIM) + s];
    }
    if (tid < ROWS) s_x[SDIM * TSTRIDE + tid] = 0.0f;
    __syncthreads();   // last full-block barrier

    // ---- Thread mapping: half (13 warps, 32 rows); gs selects a 4-row subgroup ----
    const int w    = tid >> 5;
    const int lane = tid & 31;
    const int half = (w >= 13) ? 1 : 0;
    const int hw   = w - half * 13;
    const int gs   = lane >> 4;
    const int sub  = lane & 15;
    int rg, j; bool dup = false;
    if (hw < 12) { rg = hw / 3; j = (hw % 3) * 16 + sub; }
    else { j = 48 + (sub & 1); rg = (sub >> 1) & 3; dup = (sub >= 8); }
    const int hbase = half * HROWS;
    const int r0 = hbase + rg * 8 + gs * 4;   // this thread's 4 rows

    const float4* pW_ih0 = (const float4*)(sm + OFF_W4_IH0) + j * W4I_S;
    const float4* pW_hh0 = (const float4*)(sm + OFF_W4_HH0) + j * W4H_S;
    const float4* pW_ih1 = (const float4*)(sm + OFF_W4_IH1) + j * W4H_S;
    const float4* pW_hh1 = (const float4*)(sm + OFF_W4_HH1) + j * W4H_S;

    // Bias packs (all 4 gates, both layers)
    const ull bi0 = pack2(s_b0[j], s_b0[j]);
    const ull bf0 = pack2(s_b0[HID + j], s_b0[HID + j]);
    const ull bg0 = pack2(s_b0[2*HID + j], s_b0[2*HID + j]);
    const ull bo0 = pack2(s_b0[3*HID + j], s_b0[3*HID + j]);
    const ull bi1 = pack2(s_b1[j], s_b1[j]);
    const ull bf1 = pack2(s_b1[HID + j], s_b1[HID + j]);
    const ull bg1 = pack2(s_b1[2*HID + j], s_b1[2*HID + j]);
    const ull bo1 = pack2(s_b1[3*HID + j], s_b1[3*HID + j]);

    float cx[2][2], cy[2][2];
    cx[0][0]=cx[0][1]=cy[0][0]=cy[0][1]=0.0f;
    cx[1][0]=cx[1][1]=cy[1][0]=cy[1][1]=0.0f;

    for (int t = 0; t < TSTEPS; t++) {
        const int pb = t & 1;
        float* h0r = s_h0b + pb * (HID * TSTRIDE);
        float* h0w = s_h0b + (pb ^ 1) * (HID * TSTRIDE);
        float* h1r = s_h1b + pb * (HID * TSTRIDE);
        float* h1w = s_h1b + (pb ^ 1) * (HID * TSTRIDE);

        ull ai[2], af[2], ag[2], ao[2];

        // ================= Layer 0 =================
        ai[0]=ai[1]=bi0; af[0]=af[1]=bf0; ag[0]=ag[1]=bg0; ao[0]=ao[1]=bo0;
        {
            const float* sx = &s_x[r0];
            #pragma unroll
            for (int k = 0; k < IN0; k++) GATEK(pW_ih0, sx, k);
        }
        {
            const float* sh = &h0r[r0];
            #pragma unroll 5
            for (int k = 0; k < HID; k++) GATEK(pW_hh0, sh, k);
        }
        EPILOGUE(0, h0w);
        half_bar(half);   // h0 rows of this half visible

        // ================= Layer 1 =================
        ai[0]=ai[1]=bi1; af[0]=af[1]=bf1; ag[0]=ag[1]=bg1; ao[0]=ao[1]=bo1;
        {
            const float* sh = &h0w[r0];
            #pragma unroll 5
            for (int k = 0; k < HID; k++) GATEK(pW_ih1, sh, k);
        }
        {
            const float* sh = &h1r[r0];
            #pragma unroll 5
            for (int k = 0; k < HID; k++) GATEK(pW_hh1, sh, k);
        }
        EPILOGUE(1, h1w);
        half_bar(half);   // h1 rows of this half visible

        // ========= fc1+fc2 fused (4 rows per warp, warps 0-7) + x for t+1 =========
        const bool has_next = (t + 1 < TSTEPS);
        // feature prefetch for this half's 32 rows (512 elems / 416 threads)
        int hidx = hw * 32 + lane;
        float f0 = 0.0f, f1 = 0.0f;
        int rA = hidx >> 4, sA = hidx & 15;
        int hidx2 = hidx + HTHREADS;
        int rB = hidx2 >> 4, sB = hidx2 & 15;
        if (has_next) {
            f0 = fbase[(size_t)(hbase + rA) * (TSTEPS * SDIM) + (size_t)(t + 1) * SDIM + sA];
            if (rB < HROWS)
                f1 = fbase[(size_t)(hbase + rB) * (TSTEPS * SDIM) + (size_t)(t + 1) * SDIM + sB];
        }

        if (hw < 8) {
            int rb = hbase + hw * 4;
            ull acc0 = 0ULL, acc1 = 0ULL;
            if (lane < FC1N) {
                float bb1 = s_bfc1[lane];
                acc0 = pack2(bb1, bb1); acc1 = acc0;
                const float* wr = &s_fc1[lane * FC1_S];
                #pragma unroll 10
                for (int k = 0; k < HID; k++) {
                    float wv = wr[k];
                    ull wp = pack2(wv, wv);
                    ulonglong2 hv = *(const ulonglong2*)&h1w[k * TSTRIDE + rb];
                    fma2(acc0, wp, hv.x);
                    fma2(acc1, wp, hv.y);
                }
                float2 u0 = unpk(acc0), u1 = unpk(acc1);
                float sc = s_fc2[lane];
                u0.x = fmaxf(u0.x, 0.0f) * sc;  u0.y = fmaxf(u0.y, 0.0f) * sc;
                u1.x = fmaxf(u1.x, 0.0f) * sc;  u1.y = fmaxf(u1.y, 0.0f) * sc;
                acc0 = pack2(u0.x, u0.y); acc1 = pack2(u1.x, u1.y);
            }
            #pragma unroll
            for (int off = 16; off > 0; off >>= 1) {
                add2(acc0, __shfl_down_sync(0xffffffffu, acc0, off));
                add2(acc1, __shfl_down_sync(0xffffffffu, acc1, off));
            }
            if (lane == 0) {
                float2 d0 = unpk(acc0), d1 = unpk(acc1);
                float bb = s_bfc2[0];
                d0.x += bb; d0.y += bb; d1.x += bb; d1.y += bb;
                float4 dd; dd.x = d0.x; dd.y = d0.y; dd.z = d1.x; dd.w = d1.y;
                *(float4*)&s_x[SDIM * TSTRIDE + rb] = dd;   // delta -> next x
                out[(size_t)(brow + rb)     * TSTEPS + t] = d0.x;
                out[(size_t)(brow + rb + 1) * TSTEPS + t] = d0.y;
                out[(size_t)(brow + rb + 2) * TSTEPS + t] = d1.x;
                out[(size_t)(brow + rb + 3) * TSTEPS + t] = d1.y;
            }
        }

        // store prefetched features for t+1 (this half's rows)
        if (has_next) {
            s_x[sA * TSTRIDE + hbase + rA] = f0;
            if (rB < HROWS)
                s_x[sB * TSTRIDE + hbase + rB] = f1;
        }
        half_bar(half);   // delta + x(t+1) visible within half
    }
}

extern "C" void kernel_launch(void* const* d_in, const int* in_sizes, int n_in,
                              void* d_out, int out_size)
{
    const float* features = (const float*)d_in[0];
    const float* w_ih0    = (const float*)d_in[1];
    const float* w_hh0    = (const float*)d_in[2];
    const float* b0       = (const float*)d_in[3];
    const float* w_ih1    = (const float*)d_in[4];
    const float* w_hh1    = (const float*)d_in[5];
    const float* b1       = (const float*)d_in[6];
    const float* w_fc1    = (const float*)d_in[7];
    const float* b_fc1    = (const float*)d_in[8];
    const float* w_fc2    = (const float*)d_in[9];
    const float* b_fc2    = (const float*)d_in[10];
    float* out = (float*)d_out;

    const int batch = in_sizes[0] / (TSTEPS * SDIM);
    const int nblocks = batch / ROWS;

    const size_t smem_bytes = SMEM_FLOATS * sizeof(float);
    cudaFuncSetAttribute(kozyra_lstm_kernel,
                         cudaFuncAttributeMaxDynamicSharedMemorySize,
                         (int)smem_bytes);

    kozyra_lstm_kernel<<<nblocks, NTHREADS, smem_bytes>>>(
        features, w_ih0, w_hh0, b0, w_ih1, w_hh1, b1,
        w_fc1, b_fc1, w_fc2, b_fc2, out);
}